// round 10
// baseline (speedup 1.0000x reference)
#include <cuda_runtime.h>
#include <math.h>

constexpr int NN = 2048;
constexpr int MM = 2048;
constexpr int DD = 16;

constexpr int BT           = 128;       // threads per block
constexpr int ROWS_PER_BLK = 16;        // rows of X per block
constexpr int COLS_PER_BLK = 2 * BT;    // 256 cols of X2 per block (2/thread)

typedef unsigned long long u64;

// ---- packed fp32x2 ops (sm_103a; ptxas never emits FFMA2 from C++) ----
#define FMA2(d, a, b, c) asm("fma.rn.f32x2 %0, %1, %2, %3;" : "=l"(d) : "l"(a), "l"(b), "l"(c))
#define MUL2(d, a, b)    asm("mul.rn.f32x2 %0, %1, %2;"     : "=l"(d) : "l"(a), "l"(b))
#define ADD2(d, a, b)    asm("add.rn.f32x2 %0, %1, %2;"     : "=l"(d) : "l"(a), "l"(b))
#define PACK2(d, lo, hi) asm("mov.b64 %0, {%1, %2};"        : "=l"(d) : "f"(lo), "f"(hi))
#define UNPACK2(lo, hi, s) asm("mov.b64 {%0, %1}, %2;" : "=f"(lo), "=f"(hi) : "l"(s))
#define EX2(d, s)        asm("ex2.approx.f32 %0, %1;"       : "=f"(d) : "f"(s))

#define LOG2E2 0x3FB8AA3B3FB8AA3BULL   // (log2e, log2e)

// ---------------------------------------------------------------------------
// out[n,m] = exp(hXs[n]+hX2s[m]+Xl_n.X2l_m) * (P[n]+Q[m]+Xl_n.(X2l_m ∘ w))
//   w_d = c1 - c2*l2_d,  c1 = 2*var*L,  c2 = 2*var,  L = sum(l2)
// Block: 16 rows x 256 cols; thread owns cols (m0, m0+1) packed as f32x2.
// Grid: (8, 128) = 1024 blocks -> 4096 warps (latency hiding).
// ---------------------------------------------------------------------------
__global__ __launch_bounds__(BT)
void fused_kernel(const float* __restrict__ X,
                  const float* __restrict__ X2,
                  const float* __restrict__ uls,
                  const float* __restrict__ uv,
                  float* __restrict__ out)
{
    __shared__ __align__(16) u64 sX2[ROWS_PER_BLK * DD];   // (x,x) dup pairs
    __shared__ float2 sHP[ROWS_PER_BLK];                   // (hn, pn) per row
    __shared__ float  sInv[DD];
    __shared__ float  sL2 [DD];
    __shared__ float  sVar;

    const int t  = threadIdx.x;
    const int rb = blockIdx.y * ROWS_PER_BLK;
    const int m0 = blockIdx.x * COLS_PER_BLK + 2 * t;

    // ---- phase 1: softplus of hyperparams (17 scalars) ----
    if (t < DD) {
        float u = uls[t];
        float s = (u > 20.f) ? u : log1pf(expf(u));
        sInv[t] = 1.f / s;
        sL2[t]  = 1.f / (s * s);
    }
    if (t == DD) {
        float u = uv[0];
        sVar = (u > 20.f) ? u : log1pf(expf(u));
    }
    __syncthreads();

    float L = 0.f;
#pragma unroll
    for (int d = 0; d < DD; ++d) L += sL2[d];
    const float var = sVar;
    const float c1  = 2.f * var * L;
    const float c2  = 2.f * var;

    // ---- phase 2a: row prep, one row per thread (t < 16) ----
    if (t < ROWS_PER_BLK) {
        const float4* xr = reinterpret_cast<const float4*>(X + (size_t)(rb + t) * DD);
        float xl[DD];
        float xs = 0.f, s1 = 0.f;
#pragma unroll
        for (int q = 0; q < DD / 4; ++q) {
            float4 v = xr[q];
            float v0 = v.x * sInv[4*q+0], v1 = v.y * sInv[4*q+1];
            float v2 = v.z * sInv[4*q+2], v3 = v.w * sInv[4*q+3];
            xl[4*q+0] = v0; xl[4*q+1] = v1; xl[4*q+2] = v2; xl[4*q+3] = v3;
            xs += v0*v0 + v1*v1 + v2*v2 + v3*v3;
            s1 += v0*v0*sL2[4*q+0] + v1*v1*sL2[4*q+1]
                + v2*v2*sL2[4*q+2] + v3*v3*sL2[4*q+3];
        }
#pragma unroll
        for (int d = 0; d < DD; ++d) {
            u64 p; PACK2(p, xl[d], xl[d]);
            sX2[t * DD + d] = p;
        }
        float hn = -0.5f * xs;
        float pn = var * (s1 + ((float)DD - 1.f - xs) * L);
        sHP[t] = make_float2(hn, pn);
    }

    // ---- phase 2b: per-thread column transform, packed operands ----
    u64 A[DD], U[DD];
    u64 Qp, Hc;
    {
        const float4* r = reinterpret_cast<const float4*>(X2 + (size_t)m0 * DD);
        float x2s0 = 0.f, s20 = 0.f, x2s1 = 0.f, s21 = 0.f;
#pragma unroll
        for (int q = 0; q < DD / 4; ++q) {
            float4 va = r[q];
            float4 vb = r[q + DD / 4];
#pragma unroll
            for (int j = 0; j < 4; ++j) {
                int d = 4 * q + j;
                float inv = sInv[d], l2d = sL2[d];
                float aj = ((j == 0) ? va.x : (j == 1) ? va.y : (j == 2) ? va.z : va.w) * inv;
                float bj = ((j == 0) ? vb.x : (j == 1) ? vb.y : (j == 2) ? vb.z : vb.w) * inv;
                x2s0 += aj * aj;  s20 += aj * aj * l2d;
                x2s1 += bj * bj;  s21 += bj * bj * l2d;
                PACK2(A[d], aj, bj);
                float w = c1 - c2 * l2d;
                u64 ww; PACK2(ww, w, w);
                MUL2(U[d], A[d], ww);
            }
        }
        PACK2(Qp, var * (s20 - x2s0 * L), var * (s21 - x2s1 * L));
        PACK2(Hc, -0.5f * x2s0, -0.5f * x2s1);
    }
    __syncthreads();

    // ---- main loop: 16 rows, 2 cols per thread, all-packed f32x2 ----
    const u64 log2e2 = LOG2E2;
#pragma unroll 4
    for (int n = 0; n < ROWS_PER_BLK; ++n) {
        const ulonglong2* xv = reinterpret_cast<const ulonglong2*>(sX2 + n * DD);
        u64 p0 = 0, p1 = 0, w0 = 0, w1 = 0;   // split chains (8 FMA2 each)
#pragma unroll
        for (int q = 0; q < 8; ++q) {
            ulonglong2 xx = xv[q];             // LDS.128: two (x,x) pairs
            FMA2(p0, xx.x, A[2*q+0], p0);  FMA2(w0, xx.x, U[2*q+0], w0);
            FMA2(p1, xx.y, A[2*q+1], p1);  FMA2(w1, xx.y, U[2*q+1], w1);
        }
        u64 d0;  ADD2(d0, p0, p1);
        u64 du;  ADD2(du, w0, w1);

        float2 hp = sHP[n];                    // single LDS.64
        u64 h2; PACK2(h2, hp.x, hp.x);
        u64 q2; PACK2(q2, hp.y, hp.y);

        u64 arg; ADD2(arg, d0, Hc); ADD2(arg, arg, h2);
        MUL2(arg, arg, log2e2);
        float g0, g1; UNPACK2(g0, g1, arg);
        float e0, e1; EX2(e0, g0); EX2(e1, g1);

        u64 poly; ADD2(poly, du, Qp); ADD2(poly, poly, q2);
        u64 E; PACK2(E, e0, e1);
        u64 o; MUL2(o, E, poly);

        *reinterpret_cast<u64*>(out + (size_t)(rb + n) * MM + m0) = o;
    }
}

// ---------------------------------------------------------------------------
extern "C" void kernel_launch(void* const* d_in, const int* in_sizes, int n_in,
                              void* d_out, int out_size)
{
    const float* X   = (const float*)d_in[0];   // (2048,16)
    const float* X2  = (const float*)d_in[1];   // (2048,16)
    const float* uls = (const float*)d_in[2];   // (16,)
    const float* uv  = (const float*)d_in[3];   // (1,)
    float* out = (float*)d_out;                 // (2048,2048)

    dim3 grid(MM / COLS_PER_BLK, NN / ROWS_PER_BLK);  // (8, 128) = 1024 blocks
    fused_kernel<<<grid, BT>>>(X, X2, uls, uv, out);
}